// round 15
// baseline (speedup 1.0000x reference)
#include <cuda_runtime.h>
#include <cuda_bf16.h>
#include <cuda_fp16.h>
#include <cstdint>

#define N_NODES 50000
#define NE      600000
#define D       128
#define SCAN_B  512
#define NSCANB  ((N_NODES + SCAN_B - 1) / SCAN_B)   // 98
#define CNT_BLK2 ((NE / 2 + 255) / 256)              // 1172 (2 edges/thread)

// ---------------------------------------------------------------------------
// Scratch (static device globals — no allocations allowed)
// g_deg / g_flag start zero (static init) and are re-zeroed at the end of
// every call by k_gather, so each kernel_launch sees them zeroed (deterministic).
// ---------------------------------------------------------------------------
__device__ int    g_deg[N_NODES];
__device__ float  g_dinv[N_NODES];
__device__ __half g_msg[(size_t)N_NODES * D];   // fp16: g[i] = dinv[i]*(x[i]@W)
__device__ int    g_rowptr[N_NODES + 1];
__device__ int    g_cursor[N_NODES];
__device__ int    g_srcidx[NE];
__device__ int    g_blocksum[NSCANB];
__device__ volatile int g_flag[NSCANB];
// W in mma.sync B-fragment layout: [kstep 8][ntile 16][lane 32] uint4
// = {hi.x, hi.y, lo.x, lo.y} -> one LDG.128 per (s, j)
__device__ uint4 g_Bfrag[8 * 16 * 32];

// ---------------------------------------------------------------------------
// bf16 helpers
// ---------------------------------------------------------------------------
__device__ __forceinline__ uint32_t bfpack(float a, float b) {
    __nv_bfloat162 h = __floats2bfloat162_rn(a, b);
    return *(uint32_t*)&h;
}
__device__ __forceinline__ uint32_t bfhi_lo(float a, float b, float& ra, float& rb) {
    __nv_bfloat162 h = __floats2bfloat162_rn(a, b);
    ra = a - __bfloat162float(h.x);
    rb = b - __bfloat162float(h.y);
    return *(uint32_t*)&h;
}

#define MMA16816(c, a0, a1, a2, a3, b0, b1)                                    \
    asm volatile(                                                              \
        "mma.sync.aligned.m16n8k16.row.col.f32.bf16.bf16.f32 "                 \
        "{%0,%1,%2,%3}, {%4,%5,%6,%7}, {%8,%9}, {%0,%1,%2,%3};"                \
        : "+f"((c)[0]), "+f"((c)[1]), "+f"((c)[2]), "+f"((c)[3])               \
        : "r"(a0), "r"(a1), "r"(a2), "r"(a3), "r"(b0), "r"(b1))

// ---------------------------------------------------------------------------
// L1 (fused): blocks [0, CNT_BLK2) count in-degree (2 edges/thread);
// block CNT_BLK2 preps W fragments (interleaved hi/lo uint4)
// ---------------------------------------------------------------------------
__global__ __launch_bounds__(256) void k_count_prep(const int* __restrict__ ei,
                                                    const float* __restrict__ W) {
    if (blockIdx.x < CNT_BLK2) {
        int i = blockIdx.x * 256 + threadIdx.x;
        if (i < NE / 2) {
            int2 d = ((const int2*)(ei + NE))[i];
            atomicAdd(&g_deg[d.x], 1);
            atomicAdd(&g_deg[d.y], 1);
        }
        return;
    }
    for (int slot = threadIdx.x; slot < 8 * 16 * 32; slot += 256) {
        int l = slot & 31;
        int j = (slot >> 5) & 15;
        int s = slot >> 9;
        int g = l >> 2, t = l & 3;
        int n  = 8 * j + g;
        int k0 = 16 * s + 2 * t;
        float w00 = W[(k0 + 0) * D + n];
        float w01 = W[(k0 + 1) * D + n];
        float w10 = W[(k0 + 8) * D + n];
        float w11 = W[(k0 + 9) * D + n];
        float r00, r01, r10, r11;
        uint4 f;
        f.x = bfhi_lo(w00, w01, r00, r01);   // hi b0
        f.y = bfhi_lo(w10, w11, r10, r11);   // hi b1
        f.z = bfpack(r00, r01);              // lo b0
        f.w = bfpack(r10, r11);              // lo b1
        g_Bfrag[slot] = f;
    }
}

// ---------------------------------------------------------------------------
// L2: exclusive scan of g_deg -> g_rowptr/g_cursor (+ dinv), single kernel
// via decoupled lookback. 98 blocks, all wave-1 resident; block b spins only
// on flags of blocks < b -> deadlock-free.
// ---------------------------------------------------------------------------
__global__ __launch_bounds__(SCAN_B) void k_scan() {
    __shared__ int s[SCAN_B];
    const int tid = threadIdx.x;
    const int bid = blockIdx.x;
    const int gid = bid * SCAN_B + tid;

    int v = (gid < N_NODES) ? g_deg[gid] : 0;
    if (gid < N_NODES) g_dinv[gid] = rsqrtf((float)(v + 1));
    s[tid] = v;
    __syncthreads();
#pragma unroll
    for (int off = 1; off < SCAN_B; off <<= 1) {
        int t = (tid >= off) ? s[tid - off] : 0;
        __syncthreads();
        s[tid] += t;
        __syncthreads();
    }
    int excl = s[tid] - v;                      // exclusive-in-block
    if (tid == SCAN_B - 1) {
        g_blocksum[bid] = s[SCAN_B - 1];
        __threadfence();
        g_flag[bid] = 1;
    }
    // lookback: thread t (< bid) fetches blocksum[t]
    int my = 0;
    if (tid < bid) {                            // bid <= 97 < SCAN_B
        while (g_flag[tid] == 0) {}
        my = g_blocksum[tid];
    }
    __syncthreads();
    s[tid] = my;
    __syncthreads();
#pragma unroll
    for (int st = SCAN_B / 2; st > 0; st >>= 1) {
        if (tid < st) s[tid] += s[tid + st];
        __syncthreads();
    }
    int off = s[0];
    if (gid < N_NODES) {
        int rp = excl + off;
        g_rowptr[gid] = rp;
        g_cursor[gid] = rp;
    }
    if (gid == 0) g_rowptr[N_NODES] = NE;
}

// ---------------------------------------------------------------------------
// L3: GEMM via mma.sync bf16x3, N-split: 64 rows x 64 cols per block.
// B fragments via single LDG.128 per (s,j). Epilogue stores fp16 messages.
// ---------------------------------------------------------------------------
#define HS 68   // uint32 row stride: 68 mod 32 = 4 -> lanes hit banks 4g+t
__global__ __launch_bounds__(128, 6) void k_gemm_mma(const float* __restrict__ x) {
    __shared__ uint32_t sHi[64 * HS];   // 17.4 KB packed bf16x2 hi
    __shared__ uint32_t sLo[64 * HS];   // 17.4 KB packed bf16x2 lo

    const int tid = threadIdx.x;
    const int w   = tid >> 5;
    const int l   = tid & 31;
    const int g   = l >> 2, t = l & 3;
    const int rblk = blockIdx.x >> 1;
    const int nh   = blockIdx.x & 1;
    const int base = rblk * 64;

    for (int i = tid; i < 64 * 32; i += 128) {      // 32 float4 per row
        int r  = i >> 5;
        int c4 = i & 31;
        float4 v = make_float4(0.f, 0.f, 0.f, 0.f);
        if (base + r < N_NODES)
            v = ((const float4*)(x + (size_t)(base + r) * D))[c4];
        float rx, ry, rz, rw;
        uint32_t h0 = bfhi_lo(v.x, v.y, rx, ry);
        uint32_t h1 = bfhi_lo(v.z, v.w, rz, rw);
        uint32_t l0 = bfpack(rx, ry);
        uint32_t l1 = bfpack(rz, rw);
        int o = r * HS + c4 * 2;
        sHi[o] = h0; sHi[o + 1] = h1;
        sLo[o] = l0; sLo[o + 1] = l1;
    }
    __syncthreads();

    float c[8][4];
#pragma unroll
    for (int j = 0; j < 8; j++)
#pragma unroll
        for (int q = 0; q < 4; q++) c[j][q] = 0.f;

    const int r0 = 16 * w + g;
    const uint32_t* Ah  = sHi + r0 * HS;
    const uint32_t* Ah8 = Ah + 8 * HS;
    const uint32_t* Al  = sLo + r0 * HS;
    const uint32_t* Al8 = Al + 8 * HS;

#pragma unroll
    for (int s = 0; s < 8; s++) {
        int kp = 8 * s + t;
        uint32_t ah0 = Ah [kp];
        uint32_t ah1 = Ah8[kp];
        uint32_t ah2 = Ah [kp + 4];
        uint32_t ah3 = Ah8[kp + 4];
        uint32_t al0 = Al [kp];
        uint32_t al1 = Al8[kp];
        uint32_t al2 = Al [kp + 4];
        uint32_t al3 = Al8[kp + 4];

        const uint4* bf = g_Bfrag + (s * 16 + nh * 8) * 32 + l;
#pragma unroll
        for (int j = 0; j < 8; j++) {
            uint4 B = bf[j * 32];                              // 1 LDG.128
            MMA16816(c[j], ah0, ah1, ah2, ah3, B.x, B.y);      // hi*hi
            MMA16816(c[j], al0, al1, al2, al3, B.x, B.y);      // lo*hi
            MMA16816(c[j], ah0, ah1, ah2, ah3, B.z, B.w);      // hi*lo
        }
    }

    int R0 = base + r0;
    int R1 = R0 + 8;
    float d0 = (R0 < N_NODES) ? g_dinv[R0] : 0.f;
    float d1 = (R1 < N_NODES) ? g_dinv[R1] : 0.f;
#pragma unroll
    for (int j = 0; j < 8; j++) {
        int col = 64 * nh + 8 * j + 2 * t;
        if (R0 < N_NODES)
            *(__half2*)(g_msg + (size_t)R0 * D + col) =
                __floats2half2_rn(c[j][0] * d0, c[j][1] * d0);
        if (R1 < N_NODES)
            *(__half2*)(g_msg + (size_t)R1 * D + col) =
                __floats2half2_rn(c[j][2] * d1, c[j][3] * d1);
    }
}

// ---------------------------------------------------------------------------
// L4: CSR fill, 2 edges per thread
// ---------------------------------------------------------------------------
__global__ __launch_bounds__(256) void k_fill(const int* __restrict__ ei) {
    int i = blockIdx.x * 256 + threadIdx.x;
    if (i >= NE / 2) return;
    int2 sv = ((const int2*)ei)[i];
    int2 dv = ((const int2*)(ei + NE))[i];
    int p0 = atomicAdd(&g_cursor[dv.x], 1);
    g_srcidx[p0] = sv.x;
    int p1 = atomicAdd(&g_cursor[dv.y], 1);
    g_srcidx[p1] = sv.y;
}

// ---------------------------------------------------------------------------
// L5: Gather — one warp per destination node, fp16 rows (256B), fp32 accum.
// out[i] = dinv[i] * (sum_{p in CSR(i)} g[src_p] + g[i]) + b
// Re-zeros g_deg and g_flag for the next call.
// ---------------------------------------------------------------------------
__device__ __forceinline__ float4 h4_to_f4(uint2 raw) {
    __half2 h0 = *(__half2*)&raw.x;
    __half2 h1 = *(__half2*)&raw.y;
    float2 f0 = __half22float2(h0);
    float2 f1 = __half22float2(h1);
    return make_float4(f0.x, f0.y, f1.x, f1.y);
}

__global__ __launch_bounds__(256) void k_gather(float* __restrict__ out,
                                                const float* __restrict__ b) {
    int w    = (blockIdx.x * 256 + threadIdx.x) >> 5;
    int lane = threadIdx.x & 31;
    if (w >= N_NODES) return;

    const uint2* gm = (const uint2*)g_msg;      // 32 uint2 (= 4 halves) per row
    float4 acc = h4_to_f4(__ldcg(gm + (size_t)w * 32 + lane));   // self loop
    int p  = g_rowptr[w];
    int pe = g_rowptr[w + 1];
    if (lane == 0) {
        g_deg[w] = 0;                           // restore invariants
        if (w < NSCANB) g_flag[w] = 0;
    }

    for (; p + 3 < pe; p += 4) {
        int s0 = g_srcidx[p];
        int s1 = g_srcidx[p + 1];
        int s2 = g_srcidx[p + 2];
        int s3 = g_srcidx[p + 3];
        float4 a0 = h4_to_f4(__ldcg(gm + (size_t)s0 * 32 + lane));
        float4 a1 = h4_to_f4(__ldcg(gm + (size_t)s1 * 32 + lane));
        float4 a2 = h4_to_f4(__ldcg(gm + (size_t)s2 * 32 + lane));
        float4 a3 = h4_to_f4(__ldcg(gm + (size_t)s3 * 32 + lane));
        acc.x += (a0.x + a1.x) + (a2.x + a3.x);
        acc.y += (a0.y + a1.y) + (a2.y + a3.y);
        acc.z += (a0.z + a1.z) + (a2.z + a3.z);
        acc.w += (a0.w + a1.w) + (a2.w + a3.w);
    }
    for (; p < pe; p++) {
        int s0 = g_srcidx[p];
        float4 a = h4_to_f4(__ldcg(gm + (size_t)s0 * 32 + lane));
        acc.x += a.x; acc.y += a.y; acc.z += a.z; acc.w += a.w;
    }

    float dv  = g_dinv[w];
    float4 bb = ((const float4*)b)[lane];
    float4 o;
    o.x = acc.x * dv + bb.x;
    o.y = acc.y * dv + bb.y;
    o.z = acc.z * dv + bb.z;
    o.w = acc.w * dv + bb.w;
    ((float4*)out)[(size_t)w * 32 + lane] = o;
}

// ---------------------------------------------------------------------------
extern "C" void kernel_launch(void* const* d_in, const int* in_sizes, int n_in,
                              void* d_out, int out_size) {
    const float* x   = (const float*)d_in[0];
    const int*   ei  = (const int*)d_in[1];    // int32 (JAX x64-disabled)
    const float* W   = (const float*)d_in[2];
    const float* b   = (const float*)d_in[3];
    float*       out = (float*)d_out;

    k_count_prep<<<CNT_BLK2 + 1, 256>>>(ei, W);                   // 1
    k_scan<<<NSCANB, SCAN_B>>>();                                 // 2
    k_gemm_mma<<<2 * ((N_NODES + 63) / 64), 128>>>(x);            // 3
    k_fill<<<(NE / 2 + 255) / 256, 256>>>(ei);                    // 4
    k_gather<<<(N_NODES * 32 + 255) / 256, 256>>>(out, b);        // 5
}

// round 16
// speedup vs baseline: 1.0031x; 1.0031x over previous
#include <cuda_runtime.h>
#include <cuda_bf16.h>
#include <cuda_fp16.h>
#include <cstdint>

#define N_NODES 50000
#define NE      600000
#define D       128
#define SCAN_B  512
#define NSCANB  ((N_NODES + SCAN_B - 1) / SCAN_B)   // 98
#define CNT_BLK ((NE + 255) / 256)                   // 2344

// ---------------------------------------------------------------------------
// Scratch (static device globals — no allocations allowed)
// g_deg starts zero (static init) and is re-zeroed at the end of every call
// by k_gather, so each kernel_launch sees deg == 0 on entry (deterministic).
// ---------------------------------------------------------------------------
__device__ int    g_deg[N_NODES];
__device__ float  g_dinv[N_NODES];
__device__ __half g_msg[(size_t)N_NODES * D];   // fp16: g[i] = dinv[i]*(x[i]@W)
__device__ int    g_rowptr[N_NODES + 1];
__device__ int    g_cursor[N_NODES];
__device__ int    g_srcidx[NE];
__device__ int    g_blocksum[128];
// W in mma.sync B-fragment layout: [kstep 8][ntile 16][lane 32] uint4
// = {hi.x, hi.y, lo.x, lo.y} -> one LDG.128 per (s, j)
__device__ uint4 g_Bfrag[8 * 16 * 32];

// ---------------------------------------------------------------------------
// bf16 helpers
// ---------------------------------------------------------------------------
__device__ __forceinline__ uint32_t bfpack(float a, float b) {
    __nv_bfloat162 h = __floats2bfloat162_rn(a, b);
    return *(uint32_t*)&h;
}
__device__ __forceinline__ uint32_t bfhi_lo(float a, float b, float& ra, float& rb) {
    __nv_bfloat162 h = __floats2bfloat162_rn(a, b);
    ra = a - __bfloat162float(h.x);
    rb = b - __bfloat162float(h.y);
    return *(uint32_t*)&h;
}

#define MMA16816(c, a0, a1, a2, a3, b0, b1)                                    \
    asm volatile(                                                              \
        "mma.sync.aligned.m16n8k16.row.col.f32.bf16.bf16.f32 "                 \
        "{%0,%1,%2,%3}, {%4,%5,%6,%7}, {%8,%9}, {%0,%1,%2,%3};"                \
        : "+f"((c)[0]), "+f"((c)[1]), "+f"((c)[2]), "+f"((c)[3])               \
        : "r"(a0), "r"(a1), "r"(a2), "r"(a3), "r"(b0), "r"(b1))

// ---------------------------------------------------------------------------
// L1 (fused): blocks [0, CNT_BLK) count in-degree; block CNT_BLK preps W frags
// ---------------------------------------------------------------------------
__global__ __launch_bounds__(256) void k_count_prep(const int* __restrict__ ei,
                                                    const float* __restrict__ W) {
    if (blockIdx.x < CNT_BLK) {
        int e = blockIdx.x * 256 + threadIdx.x;
        if (e < NE) atomicAdd(&g_deg[ei[NE + e]], 1);
        return;
    }
    for (int slot = threadIdx.x; slot < 8 * 16 * 32; slot += 256) {
        int l = slot & 31;
        int j = (slot >> 5) & 15;
        int s = slot >> 9;
        int g = l >> 2, t = l & 3;
        int n  = 8 * j + g;
        int k0 = 16 * s + 2 * t;
        float w00 = W[(k0 + 0) * D + n];
        float w01 = W[(k0 + 1) * D + n];
        float w10 = W[(k0 + 8) * D + n];
        float w11 = W[(k0 + 9) * D + n];
        float r00, r01, r10, r11;
        uint4 f;
        f.x = bfhi_lo(w00, w01, r00, r01);   // hi b0
        f.y = bfhi_lo(w10, w11, r10, r11);   // hi b1
        f.z = bfpack(r00, r01);              // lo b0
        f.w = bfpack(r10, r11);              // lo b1
        g_Bfrag[slot] = f;
    }
}

// ---------------------------------------------------------------------------
// L2: block-level exclusive scan of g_deg (+ fused dinv)
// ---------------------------------------------------------------------------
__global__ __launch_bounds__(SCAN_B) void k_scan_block() {
    __shared__ int s[SCAN_B];
    int gid = blockIdx.x * SCAN_B + threadIdx.x;
    int v = (gid < N_NODES) ? g_deg[gid] : 0;
    if (gid < N_NODES) g_dinv[gid] = rsqrtf((float)(v + 1));   // fused
    s[threadIdx.x] = v;
    __syncthreads();
#pragma unroll
    for (int off = 1; off < SCAN_B; off <<= 1) {
        int t = (threadIdx.x >= off) ? s[threadIdx.x - off] : 0;
        __syncthreads();
        s[threadIdx.x] += t;
        __syncthreads();
    }
    if (gid < N_NODES) g_rowptr[gid] = s[threadIdx.x] - v;
    if (threadIdx.x == SCAN_B - 1) g_blocksum[blockIdx.x] = s[SCAN_B - 1];
}

// ---------------------------------------------------------------------------
// L3 (fused top+fix): add cross-block offsets, init cursor
// ---------------------------------------------------------------------------
__global__ __launch_bounds__(256) void k_scan_fix() {
    __shared__ int ss[128];
    int tid = threadIdx.x;
    int gid = blockIdx.x * 256 + tid;
    if (tid < 128) ss[tid] = (tid < NSCANB) ? g_blocksum[tid] : 0;
    __syncthreads();
    if (gid < N_NODES) {
        int blk = gid / SCAN_B;
        int off = 0;
        for (int i = 0; i < blk; i++) off += ss[i];
        int rp = g_rowptr[gid] + off;
        g_rowptr[gid] = rp;
        g_cursor[gid] = rp;
    }
    if (gid == 0) g_rowptr[N_NODES] = NE;
}

// ---------------------------------------------------------------------------
// L4: GEMM via mma.sync bf16x3, N-split: 64 rows x 64 cols per block.
// B fragments via single LDG.128 per (s,j). Epilogue stores fp16 messages.
// ---------------------------------------------------------------------------
#define HS 68   // uint32 row stride: 68 mod 32 = 4 -> lanes hit banks 4g+t
__global__ __launch_bounds__(128, 6) void k_gemm_mma(const float* __restrict__ x) {
    __shared__ uint32_t sHi[64 * HS];   // 17.4 KB packed bf16x2 hi
    __shared__ uint32_t sLo[64 * HS];   // 17.4 KB packed bf16x2 lo

    const int tid = threadIdx.x;
    const int w   = tid >> 5;
    const int l   = tid & 31;
    const int g   = l >> 2, t = l & 3;
    const int rblk = blockIdx.x >> 1;
    const int nh   = blockIdx.x & 1;
    const int base = rblk * 64;

    for (int i = tid; i < 64 * 32; i += 128) {      // 32 float4 per row
        int r  = i >> 5;
        int c4 = i & 31;
        float4 v = make_float4(0.f, 0.f, 0.f, 0.f);
        if (base + r < N_NODES)
            v = ((const float4*)(x + (size_t)(base + r) * D))[c4];
        float rx, ry, rz, rw;
        uint32_t h0 = bfhi_lo(v.x, v.y, rx, ry);
        uint32_t h1 = bfhi_lo(v.z, v.w, rz, rw);
        uint32_t l0 = bfpack(rx, ry);
        uint32_t l1 = bfpack(rz, rw);
        int o = r * HS + c4 * 2;
        sHi[o] = h0; sHi[o + 1] = h1;
        sLo[o] = l0; sLo[o + 1] = l1;
    }
    __syncthreads();

    float c[8][4];
#pragma unroll
    for (int j = 0; j < 8; j++)
#pragma unroll
        for (int q = 0; q < 4; q++) c[j][q] = 0.f;

    const int r0 = 16 * w + g;
    const uint32_t* Ah  = sHi + r0 * HS;
    const uint32_t* Ah8 = Ah + 8 * HS;
    const uint32_t* Al  = sLo + r0 * HS;
    const uint32_t* Al8 = Al + 8 * HS;

#pragma unroll
    for (int s = 0; s < 8; s++) {
        int kp = 8 * s + t;
        uint32_t ah0 = Ah [kp];
        uint32_t ah1 = Ah8[kp];
        uint32_t ah2 = Ah [kp + 4];
        uint32_t ah3 = Ah8[kp + 4];
        uint32_t al0 = Al [kp];
        uint32_t al1 = Al8[kp];
        uint32_t al2 = Al [kp + 4];
        uint32_t al3 = Al8[kp + 4];

        const uint4* bf = g_Bfrag + (s * 16 + nh * 8) * 32 + l;
#pragma unroll
        for (int j = 0; j < 8; j++) {
            uint4 B = bf[j * 32];                              // 1 LDG.128
            MMA16816(c[j], ah0, ah1, ah2, ah3, B.x, B.y);      // hi*hi
            MMA16816(c[j], al0, al1, al2, al3, B.x, B.y);      // lo*hi
            MMA16816(c[j], ah0, ah1, ah2, ah3, B.z, B.w);      // hi*lo
        }
    }

    int R0 = base + r0;
    int R1 = R0 + 8;
    float d0 = (R0 < N_NODES) ? g_dinv[R0] : 0.f;
    float d1 = (R1 < N_NODES) ? g_dinv[R1] : 0.f;
#pragma unroll
    for (int j = 0; j < 8; j++) {
        int col = 64 * nh + 8 * j + 2 * t;
        if (R0 < N_NODES)
            *(__half2*)(g_msg + (size_t)R0 * D + col) =
                __floats2half2_rn(c[j][0] * d0, c[j][1] * d0);
        if (R1 < N_NODES)
            *(__half2*)(g_msg + (size_t)R1 * D + col) =
                __floats2half2_rn(c[j][2] * d1, c[j][3] * d1);
    }
}

// L5: CSR fill (scalar, 1 edge/thread — the int2 variant regressed)
__global__ __launch_bounds__(256) void k_fill(const int* __restrict__ ei) {
    int e = blockIdx.x * blockDim.x + threadIdx.x;
    if (e >= NE) return;
    int pos = atomicAdd(&g_cursor[ei[NE + e]], 1);
    g_srcidx[pos] = ei[e];
}

// ---------------------------------------------------------------------------
// L6: Gather — one warp per destination node, fp16 rows (256B), fp32 accum.
// out[i] = dinv[i] * (sum_{p in CSR(i)} g[src_p] + g[i]) + b
// Re-zeros g_deg for the next call (invariant: deg==0 on entry).
// ---------------------------------------------------------------------------
__device__ __forceinline__ float4 h4_to_f4(uint2 raw) {
    __half2 h0 = *(__half2*)&raw.x;
    __half2 h1 = *(__half2*)&raw.y;
    float2 f0 = __half22float2(h0);
    float2 f1 = __half22float2(h1);
    return make_float4(f0.x, f0.y, f1.x, f1.y);
}

__global__ __launch_bounds__(256) void k_gather(float* __restrict__ out,
                                                const float* __restrict__ b) {
    int w    = (blockIdx.x * 256 + threadIdx.x) >> 5;
    int lane = threadIdx.x & 31;
    if (w >= N_NODES) return;

    const uint2* gm = (const uint2*)g_msg;      // 32 uint2 (= 4 halves) per row
    float4 acc = h4_to_f4(__ldcg(gm + (size_t)w * 32 + lane));   // self loop
    int p  = g_rowptr[w];
    int pe = g_rowptr[w + 1];
    if (lane == 0) g_deg[w] = 0;                // restore invariant for next call

    for (; p + 3 < pe; p += 4) {
        int s0 = g_srcidx[p];
        int s1 = g_srcidx[p + 1];
        int s2 = g_srcidx[p + 2];
        int s3 = g_srcidx[p + 3];
        float4 a0 = h4_to_f4(__ldcg(gm + (size_t)s0 * 32 + lane));
        float4 a1 = h4_to_f4(__ldcg(gm + (size_t)s1 * 32 + lane));
        float4 a2 = h4_to_f4(__ldcg(gm + (size_t)s2 * 32 + lane));
        float4 a3 = h4_to_f4(__ldcg(gm + (size_t)s3 * 32 + lane));
        acc.x += (a0.x + a1.x) + (a2.x + a3.x);
        acc.y += (a0.y + a1.y) + (a2.y + a3.y);
        acc.z += (a0.z + a1.z) + (a2.z + a3.z);
        acc.w += (a0.w + a1.w) + (a2.w + a3.w);
    }
    for (; p < pe; p++) {
        int s0 = g_srcidx[p];
        float4 a = h4_to_f4(__ldcg(gm + (size_t)s0 * 32 + lane));
        acc.x += a.x; acc.y += a.y; acc.z += a.z; acc.w += a.w;
    }

    float dv  = g_dinv[w];
    float4 bb = ((const float4*)b)[lane];
    float4 o;
    o.x = acc.x * dv + bb.x;
    o.y = acc.y * dv + bb.y;
    o.z = acc.z * dv + bb.z;
    o.w = acc.w * dv + bb.w;
    ((float4*)out)[(size_t)w * 32 + lane] = o;
}

// ---------------------------------------------------------------------------
extern "C" void kernel_launch(void* const* d_in, const int* in_sizes, int n_in,
                              void* d_out, int out_size) {
    const float* x   = (const float*)d_in[0];
    const int*   ei  = (const int*)d_in[1];    // int32 (JAX x64-disabled)
    const float* W   = (const float*)d_in[2];
    const float* b   = (const float*)d_in[3];
    float*       out = (float*)d_out;

    k_count_prep<<<CNT_BLK + 1, 256>>>(ei, W);                    // 1
    k_scan_block<<<NSCANB, SCAN_B>>>();                           // 2
    k_scan_fix<<<(N_NODES + 255) / 256, 256>>>();                 // 3
    k_gemm_mma<<<2 * ((N_NODES + 63) / 64), 128>>>(x);            // 4 <- profiled
    k_fill<<<(NE + 255) / 256, 256>>>(ei);                        // 5
    k_gather<<<(N_NODES * 32 + 255) / 256, 256>>>(out, b);        // 6
}

// round 17
// speedup vs baseline: 1.2464x; 1.2425x over previous
#include <cuda_runtime.h>
#include <cuda_bf16.h>
#include <cuda_fp16.h>
#include <cstdint>

#define N_NODES 50000
#define NE      600000
#define D       128
#define SCAN_B  512
#define NSCANB  ((N_NODES + SCAN_B - 1) / SCAN_B)   // 98
#define CNT_BLK ((NE + 255) / 256)                   // 2344

// ---------------------------------------------------------------------------
// Scratch (static device globals — no allocations allowed)
// g_deg starts zero (static init) and is re-zeroed at the end of every call
// by k_gather, so each kernel_launch sees deg == 0 on entry (deterministic).
// ---------------------------------------------------------------------------
__device__ int    g_deg[N_NODES];
__device__ float  g_dinv[N_NODES];
__device__ __half g_msg[(size_t)N_NODES * D];   // fp16: g[i] = dinv[i]*(x[i]@W)
__device__ int    g_rowptr[N_NODES + 1];
__device__ int    g_cursor[N_NODES];
__device__ int    g_srcidx[NE];
__device__ int    g_blocksum[128];
// W in mma.sync B-fragment layout: [kstep 8][ntile 16][lane 32] uint2, hi & lo
__device__ uint2 g_Bhi[8 * 16 * 32];
__device__ uint2 g_Blo[8 * 16 * 32];

// ---------------------------------------------------------------------------
// bf16 helpers
// ---------------------------------------------------------------------------
__device__ __forceinline__ uint32_t bfpack(float a, float b) {
    __nv_bfloat162 h = __floats2bfloat162_rn(a, b);
    return *(uint32_t*)&h;
}
__device__ __forceinline__ uint32_t bfhi_lo(float a, float b, float& ra, float& rb) {
    __nv_bfloat162 h = __floats2bfloat162_rn(a, b);
    ra = a - __bfloat162float(h.x);
    rb = b - __bfloat162float(h.y);
    return *(uint32_t*)&h;
}

#define MMA16816(c, a0, a1, a2, a3, b0, b1)                                    \
    asm volatile(                                                              \
        "mma.sync.aligned.m16n8k16.row.col.f32.bf16.bf16.f32 "                 \
        "{%0,%1,%2,%3}, {%4,%5,%6,%7}, {%8,%9}, {%0,%1,%2,%3};"                \
        : "+f"((c)[0]), "+f"((c)[1]), "+f"((c)[2]), "+f"((c)[3])               \
        : "r"(a0), "r"(a1), "r"(a2), "r"(a3), "r"(b0), "r"(b1))

// ---------------------------------------------------------------------------
// L1 (fused): blocks [0, CNT_BLK) count in-degree; block CNT_BLK preps W frags
// ---------------------------------------------------------------------------
__global__ __launch_bounds__(256) void k_count_prep(const int* __restrict__ ei,
                                                    const float* __restrict__ W) {
    if (blockIdx.x < CNT_BLK) {
        int e = blockIdx.x * 256 + threadIdx.x;
        if (e < NE) atomicAdd(&g_deg[ei[NE + e]], 1);
        return;
    }
    for (int slot = threadIdx.x; slot < 8 * 16 * 32; slot += 256) {
        int l = slot & 31;
        int j = (slot >> 5) & 15;
        int s = slot >> 9;
        int g = l >> 2, t = l & 3;
        int n  = 8 * j + g;
        int k0 = 16 * s + 2 * t;
        float w00 = W[(k0 + 0) * D + n];
        float w01 = W[(k0 + 1) * D + n];
        float w10 = W[(k0 + 8) * D + n];
        float w11 = W[(k0 + 9) * D + n];
        float r00, r01, r10, r11;
        uint2 hi, lo;
        hi.x = bfhi_lo(w00, w01, r00, r01);
        hi.y = bfhi_lo(w10, w11, r10, r11);
        lo.x = bfpack(r00, r01);
        lo.y = bfpack(r10, r11);
        g_Bhi[slot] = hi;
        g_Blo[slot] = lo;
    }
}

// ---------------------------------------------------------------------------
// L2: block-level exclusive scan of g_deg (+ fused dinv)
// ---------------------------------------------------------------------------
__global__ __launch_bounds__(SCAN_B) void k_scan_block() {
    __shared__ int s[SCAN_B];
    int gid = blockIdx.x * SCAN_B + threadIdx.x;
    int v = (gid < N_NODES) ? g_deg[gid] : 0;
    if (gid < N_NODES) g_dinv[gid] = rsqrtf((float)(v + 1));   // fused
    s[threadIdx.x] = v;
    __syncthreads();
#pragma unroll
    for (int off = 1; off < SCAN_B; off <<= 1) {
        int t = (threadIdx.x >= off) ? s[threadIdx.x - off] : 0;
        __syncthreads();
        s[threadIdx.x] += t;
        __syncthreads();
    }
    if (gid < N_NODES) g_rowptr[gid] = s[threadIdx.x] - v;
    if (threadIdx.x == SCAN_B - 1) g_blocksum[blockIdx.x] = s[SCAN_B - 1];
}

// ---------------------------------------------------------------------------
// L3 (fused top+fix): add cross-block offsets, init cursor
// ---------------------------------------------------------------------------
__global__ __launch_bounds__(256) void k_scan_fix() {
    __shared__ int ss[128];
    int tid = threadIdx.x;
    int gid = blockIdx.x * 256 + tid;
    if (tid < 128) ss[tid] = (tid < NSCANB) ? g_blocksum[tid] : 0;
    __syncthreads();
    if (gid < N_NODES) {
        int blk = gid / SCAN_B;
        int off = 0;
        for (int i = 0; i < blk; i++) off += ss[i];
        int rp = g_rowptr[gid] + off;
        g_rowptr[gid] = rp;
        g_cursor[gid] = rp;
    }
    if (gid == 0) g_rowptr[N_NODES] = NE;
}

// ---------------------------------------------------------------------------
// L4: GEMM via mma.sync bf16x3, N-split: 64 rows x 64 cols per block.
// Epilogue stores fp16 messages.
// ---------------------------------------------------------------------------
#define HS 68   // uint32 row stride: 68 mod 32 = 4 -> lanes hit banks 4g+t
__global__ __launch_bounds__(128, 6) void k_gemm_mma(const float* __restrict__ x) {
    __shared__ uint32_t sHi[64 * HS];   // 17.4 KB packed bf16x2 hi
    __shared__ uint32_t sLo[64 * HS];   // 17.4 KB packed bf16x2 lo

    const int tid = threadIdx.x;
    const int w   = tid >> 5;
    const int l   = tid & 31;
    const int g   = l >> 2, t = l & 3;
    const int rblk = blockIdx.x >> 1;
    const int nh   = blockIdx.x & 1;
    const int base = rblk * 64;

    for (int i = tid; i < 64 * 32; i += 128) {      // 32 float4 per row
        int r  = i >> 5;
        int c4 = i & 31;
        float4 v = make_float4(0.f, 0.f, 0.f, 0.f);
        if (base + r < N_NODES)
            v = ((const float4*)(x + (size_t)(base + r) * D))[c4];
        float rx, ry, rz, rw;
        uint32_t h0 = bfhi_lo(v.x, v.y, rx, ry);
        uint32_t h1 = bfhi_lo(v.z, v.w, rz, rw);
        uint32_t l0 = bfpack(rx, ry);
        uint32_t l1 = bfpack(rz, rw);
        int o = r * HS + c4 * 2;
        sHi[o] = h0; sHi[o + 1] = h1;
        sLo[o] = l0; sLo[o + 1] = l1;
    }
    __syncthreads();

    float c[8][4];
#pragma unroll
    for (int j = 0; j < 8; j++)
#pragma unroll
        for (int q = 0; q < 4; q++) c[j][q] = 0.f;

    const int r0 = 16 * w + g;
    const uint32_t* Ah  = sHi + r0 * HS;
    const uint32_t* Ah8 = Ah + 8 * HS;
    const uint32_t* Al  = sLo + r0 * HS;
    const uint32_t* Al8 = Al + 8 * HS;

#pragma unroll
    for (int s = 0; s < 8; s++) {
        int kp = 8 * s + t;
        uint32_t ah0 = Ah [kp];
        uint32_t ah1 = Ah8[kp];
        uint32_t ah2 = Ah [kp + 4];
        uint32_t ah3 = Ah8[kp + 4];
        uint32_t al0 = Al [kp];
        uint32_t al1 = Al8[kp];
        uint32_t al2 = Al [kp + 4];
        uint32_t al3 = Al8[kp + 4];

        const uint2* bh = g_Bhi + (s * 16 + nh * 8) * 32 + l;
        const uint2* bl = g_Blo + (s * 16 + nh * 8) * 32 + l;
#pragma unroll
        for (int j = 0; j < 8; j++) {
            uint2 B  = bh[j * 32];
            uint2 Bl = bl[j * 32];
            MMA16816(c[j], ah0, ah1, ah2, ah3, B.x,  B.y);   // hi*hi
            MMA16816(c[j], al0, al1, al2, al3, B.x,  B.y);   // lo*hi
            MMA16816(c[j], ah0, ah1, ah2, ah3, Bl.x, Bl.y);  // hi*lo
        }
    }

    int R0 = base + r0;
    int R1 = R0 + 8;
    float d0 = (R0 < N_NODES) ? g_dinv[R0] : 0.f;
    float d1 = (R1 < N_NODES) ? g_dinv[R1] : 0.f;
#pragma unroll
    for (int j = 0; j < 8; j++) {
        int col = 64 * nh + 8 * j + 2 * t;
        if (R0 < N_NODES)
            *(__half2*)(g_msg + (size_t)R0 * D + col) =
                __floats2half2_rn(c[j][0] * d0, c[j][1] * d0);
        if (R1 < N_NODES)
            *(__half2*)(g_msg + (size_t)R1 * D + col) =
                __floats2half2_rn(c[j][2] * d1, c[j][3] * d1);
    }
}

// L5: CSR fill
__global__ __launch_bounds__(256) void k_fill(const int* __restrict__ ei) {
    int e = blockIdx.x * blockDim.x + threadIdx.x;
    if (e >= NE) return;
    int pos = atomicAdd(&g_cursor[ei[NE + e]], 1);
    g_srcidx[pos] = ei[e];
}

// ---------------------------------------------------------------------------
// L6: Gather — one warp per destination node, fp16 rows (256B), fp32 accum.
// out[i] = dinv[i] * (sum_{p in CSR(i)} g[src_p] + g[i]) + b
// Re-zeros g_deg for the next call (invariant: deg==0 on entry).
// ---------------------------------------------------------------------------
__device__ __forceinline__ float4 h4_to_f4(uint2 raw) {
    __half2 h0 = *(__half2*)&raw.x;
    __half2 h1 = *(__half2*)&raw.y;
    float2 f0 = __half22float2(h0);
    float2 f1 = __half22float2(h1);
    return make_float4(f0.x, f0.y, f1.x, f1.y);
}

__global__ __launch_bounds__(256) void k_gather(float* __restrict__ out,
                                                const float* __restrict__ b) {
    int w    = (blockIdx.x * 256 + threadIdx.x) >> 5;
    int lane = threadIdx.x & 31;
    if (w >= N_NODES) return;

    const uint2* gm = (const uint2*)g_msg;      // 32 uint2 (= 4 halves) per row
    float4 acc = h4_to_f4(__ldcg(gm + (size_t)w * 32 + lane));   // self loop
    int p  = g_rowptr[w];
    int pe = g_rowptr[w + 1];
    if (lane == 0) g_deg[w] = 0;                // restore invariant for next call

    for (; p + 3 < pe; p += 4) {
        int s0 = g_srcidx[p];
        int s1 = g_srcidx[p + 1];
        int s2 = g_srcidx[p + 2];
        int s3 = g_srcidx[p + 3];
        float4 a0 = h4_to_f4(__ldcg(gm + (size_t)s0 * 32 + lane));
        float4 a1 = h4_to_f4(__ldcg(gm + (size_t)s1 * 32 + lane));
        float4 a2 = h4_to_f4(__ldcg(gm + (size_t)s2 * 32 + lane));
        float4 a3 = h4_to_f4(__ldcg(gm + (size_t)s3 * 32 + lane));
        acc.x += (a0.x + a1.x) + (a2.x + a3.x);
        acc.y += (a0.y + a1.y) + (a2.y + a3.y);
        acc.z += (a0.z + a1.z) + (a2.z + a3.z);
        acc.w += (a0.w + a1.w) + (a2.w + a3.w);
    }
    for (; p < pe; p++) {
        int s0 = g_srcidx[p];
        float4 a = h4_to_f4(__ldcg(gm + (size_t)s0 * 32 + lane));
        acc.x += a.x; acc.y += a.y; acc.z += a.z; acc.w += a.w;
    }

    float dv  = g_dinv[w];
    float4 bb = ((const float4*)b)[lane];
    float4 o;
    o.x = acc.x * dv + bb.x;
    o.y = acc.y * dv + bb.y;
    o.z = acc.z * dv + bb.z;
    o.w = acc.w * dv + bb.w;
    ((float4*)out)[(size_t)w * 32 + lane] = o;
}

// ---------------------------------------------------------------------------
extern "C" void kernel_launch(void* const* d_in, const int* in_sizes, int n_in,
                              void* d_out, int out_size) {
    const float* x   = (const float*)d_in[0];
    const int*   ei  = (const int*)d_in[1];    // int32 (JAX x64-disabled)
    const float* W   = (const float*)d_in[2];
    const float* b   = (const float*)d_in[3];
    float*       out = (float*)d_out;

    k_count_prep<<<CNT_BLK + 1, 256>>>(ei, W);                    // 1
    k_scan_block<<<NSCANB, SCAN_B>>>();                           // 2
    k_scan_fix<<<(N_NODES + 255) / 256, 256>>>();                 // 3
    k_gemm_mma<<<2 * ((N_NODES + 63) / 64), 128>>>(x);            // 4 <- profiled
    k_fill<<<(NE + 255) / 256, 256>>>(ei);                        // 5
    k_gather<<<(N_NODES * 32 + 255) / 256, 256>>>(out, b);        // 6
}